// round 10
// baseline (speedup 1.0000x reference)
#include <cuda_runtime.h>
#include <cuda_fp16.h>
#include <cstdint>

// ---------------- problem constants ----------------
#define HW    112
#define IMG   (HW*HW)          // 12544
#define NB    32
#define CIN   128
#define COUT  256
#define NPOS  (NB*IMG)         // 401408
#define KTOT  1152             // 3*3*128

// ---------------- scratch ( __device__ globals ) ----------------
__device__ __half g_xq[(size_t)NPOS * CIN];           // fp16 copy of x
__device__ __half g_wbin[(size_t)COUT * KTOT];        // sign(w) fp16, [co][tap*128+c]

// ---------------- helpers (sm_80-level base ISA) ----------------
__device__ __forceinline__ uint32_t smem_to_u32(const void* p) {
    uint32_t a;
    asm("{ .reg .u64 t; cvta.to.shared.u64 t, %1; cvt.u32.u64 %0, t; }" : "=r"(a) : "l"(p));
    return a;
}

__device__ __forceinline__ void cp16(uint32_t dst, const void* src, bool pred) {
    int sz = pred ? 16 : 0;     // src-size 0 -> 16B zfill (src not accessed)
    asm volatile("cp.async.cg.shared.global [%0], [%1], 16, %2;"
                 :: "r"(dst), "l"(src), "r"(sz) : "memory");
}

#define CP_COMMIT() asm volatile("cp.async.commit_group;" ::: "memory")
#define CP_WAIT1()  asm volatile("cp.async.wait_group 1;" ::: "memory")

__device__ __forceinline__ void ldsm4(uint32_t* r, uint32_t addr) {
    asm volatile("ldmatrix.sync.aligned.m8n8.x4.shared.b16 {%0,%1,%2,%3}, [%4];"
                 : "=r"(r[0]), "=r"(r[1]), "=r"(r[2]), "=r"(r[3]) : "r"(addr));
}

__device__ __forceinline__ void mma_f16(float* c, const uint32_t* a,
                                        uint32_t b0, uint32_t b1) {
    asm volatile(
        "mma.sync.aligned.m16n8k16.row.col.f32.f16.f16.f32 "
        "{%0,%1,%2,%3}, {%4,%5,%6,%7}, {%8,%9}, {%0,%1,%2,%3};"
        : "+f"(c[0]), "+f"(c[1]), "+f"(c[2]), "+f"(c[3])
        : "r"(a[0]), "r"(a[1]), "r"(a[2]), "r"(a[3]), "r"(b0), "r"(b1));
}

// ---------------- SMEM layout ----------------
// A halo (loaded once): 10h x 18w positions x 256B (two 128B chh rows) = 46080 B
//   physical 128B row index R = halo_row*2 + chh ; 16B unit u stored at
//   R*128 + ((u ^ (halo_row & 7)) << 4)   (swizzle keyed on halo_row!)
// B stages: 3 x 16384 B (128 co-rows x 128B), unit u at r*128 + ((u^(r&7))<<4)
static constexpr int HLO_W    = 18;
static constexpr int A_ROWS   = 180;          // 10*18
static constexpr int A_BYTES  = A_ROWS * 256; // 46080 (1024-aligned)
static constexpr int B_STAGE  = 16384;
static constexpr int DYN_SMEM = A_BYTES + 3 * B_STAGE;   // 95232 -> 2 CTAs/SM

// ---------------- prep kernels ----------------
__global__ void binarize_kernel(const float* __restrict__ w) {
    int i = blockIdx.x * blockDim.x + threadIdx.x;
    if (i >= COUT * KTOT) return;
    int k  = i >> 8;          // HWIO: co fastest
    int co = i & 255;
    float v = w[i];
    float s = (v > 0.f) ? 1.f : ((v < 0.f) ? -1.f : 0.f);
    g_wbin[co * KTOT + k] = __float2half_rn(s);
}

__global__ void quant_kernel(const float4* __restrict__ x) {
    int i = blockIdx.x * blockDim.x + threadIdx.x;
    if (i >= (NPOS * CIN) / 4) return;
    float4 v = x[i];
    __half2 p0 = make_half2(__float2half_rn(v.x), __float2half_rn(v.y));
    __half2 p1 = make_half2(__float2half_rn(v.z), __float2half_rn(v.w));
    uint2 pk;
    pk.x = *(uint32_t*)&p0;
    pk.y = *(uint32_t*)&p1;
    ((uint2*)g_xq)[i] = pk;
}

// ---------------- main implicit-GEMM conv (fp16 HMMA, A-halo resident) ----------------
// Launched twice (nt = 0,1). CTA tile: M=128 spatial positions as an 8h x 16w
// block of one image, N=128 output channels. 256 threads, 2 CTAs/SM.
// 8 warps, warp tile 64x32 (2 M-warps x 4 N-warps).
// A halo staged once (borders zero-filled); 18 K-chunks stream only B.
__global__ __launch_bounds__(256, 2)
void conv_kernel(float* __restrict__ out, int nt) {
    extern __shared__ char smem[];
    const uint32_t smem_u = smem_to_u32(smem);
    const int tid  = threadIdx.x;
    const int wid  = tid >> 5;
    const int lane = tid & 31;

    // ---- decode CTA -> (n, h0, w0) ----
    int bx   = blockIdx.x;
    int wblk = bx % 7;  int t1 = bx / 7;
    int hblk = t1 % 14; int n  = t1 / 14;
    const int h0 = hblk * 8;
    const int w0 = wblk * 16;

    // ---- B load slots (per chunk; 1024 uint4 / 256 thr) ----
    int bsrc[4];
    uint32_t dstB[4];
#pragma unroll
    for (int j = 0; j < 4; ++j) {
        int s = tid + j * 256;
        int r = s >> 3;
        int u = s & 7;
        bsrc[j] = (nt * 128 + r) * KTOT + u * 8;             // in halfs
        dstB[j] = r * 128 + ((u ^ (r & 7)) << 4);
    }

    // ---- issue A halo load ONCE (2880 16B units, 12 slots) ----
#pragma unroll
    for (int j = 0; j < 12; ++j) {
        int s = tid + j * 256;
        if (s < 2880) {
            int u   = s & 7;
            int Rr  = s >> 3;            // physical 128B row 0..359
            int chh = Rr & 1;
            int hr  = Rr >> 1;           // halo row 0..179
            int hy  = hr / HLO_W;
            int hx  = hr - hy * HLO_W;
            int gh  = h0 + hy - 1;
            int gw  = w0 + hx - 1;
            bool ok = ((unsigned)gh < (unsigned)HW) && ((unsigned)gw < (unsigned)HW);
            const __half* src = g_xq + ((size_t)((n * HW + gh) * HW + gw)) * CIN
                                + chh * 64 + u * 8;
            uint32_t dst = smem_u + Rr * 128 + ((u ^ (hr & 7)) << 4);
            cp16(dst, src, ok);
        }
    }
    CP_COMMIT();                         // group: A halo

    // ---- B producer ----
    auto issue_B = [&](int it, int stage) {
        int tap = it >> 1;
        int chh = it & 1;
        const int woff = tap * CIN + chh * 64;               // halfs
        const uint32_t bb = smem_u + A_BYTES + stage * B_STAGE;
#pragma unroll
        for (int j = 0; j < 4; ++j)
            cp16(bb + dstB[j], g_wbin + bsrc[j] + woff, true);
    };

    issue_B(0, 0); CP_COMMIT();
    issue_B(1, 1); CP_COMMIT();

    // ---- warp tiling: 2 M-warps x 4 N-warps ----
    const int wm = (wid & 1) * 64;      // 0 or 64
    const int wn = (wid >> 1) * 32;     // 0,32,64,96

    // per-lane fragment row bases (fixed)
    int abase[4];                        // halo-row base per mf (tap-independent)
#pragma unroll
    for (int mf = 0; mf < 4; ++mf) {
        int rr = wm + mf * 16 + (lane & 15);   // m-row 0..127
        abase[mf] = (rr >> 4) * HLO_W + (rr & 15);   // hi*18 + wi
    }
    int bbase[2];
#pragma unroll
    for (int q = 0; q < 2; ++q)
        bbase[q] = wn + q * 16 + (lane & 15);
    const int lhalf = lane >> 4;         // 16B half select

    float acc[4][4][4];
#pragma unroll
    for (int i = 0; i < 4; ++i)
#pragma unroll
        for (int j = 0; j < 4; ++j)
#pragma unroll
            for (int q = 0; q < 4; ++q) acc[i][j][q] = 0.f;

    for (int it = 0; it < 18; ++it) {
        CP_WAIT1();                 // chunk `it` B (and A) resident
        __syncthreads();            // all warps past chunk it-1; its stage free
        if (it + 2 < 18) issue_B(it + 2, (it + 2) % 3);
        CP_COMMIT();

        const int tap = it >> 1;
        const int chh = it & 1;
        const int kh  = tap / 3, kw = tap - kh * 3;
        const int tapoff = kh * HLO_W + kw;          // halo-row shift
        const uint32_t Bbase = smem_u + A_BYTES + (it % 3) * B_STAGE;

#pragma unroll
        for (int i = 0; i < 4; ++i) {
            const int ks = (i + wid) & 3;            // per-warp phase skew
            const int ku = ks * 2 + lhalf;           // 16B unit base of this k16
            uint32_t a[4][4];
#pragma unroll
            for (int mf = 0; mf < 4; ++mf) {
                int hrow = abase[mf] + tapoff;
                uint32_t addr = smem_u + (uint32_t)(hrow * 256 + chh * 128)
                              + (uint32_t)(((ku ^ (hrow & 7)) << 4));
                ldsm4(a[mf], addr);
            }
            uint32_t b[2][4];
#pragma unroll
            for (int q = 0; q < 2; ++q) {
                int row = bbase[q];
                uint32_t addr = Bbase + (uint32_t)(row * 128)
                              + (uint32_t)(((ku ^ (row & 7)) << 4));
                ldsm4(b[q], addr);
            }
#pragma unroll
            for (int mf = 0; mf < 4; ++mf)
#pragma unroll
                for (int nb = 0; nb < 4; ++nb) {
                    int q = nb >> 1, jj = nb & 1;
                    mma_f16(acc[mf][nb], a[mf], b[q][jj], b[q][jj + 2]);
                }
        }
    }

    // ---- epilogue: registers -> gmem ----
    const int r0 = lane >> 2;            // 0..7  (= wi within 16)
    const int c0 = (lane & 3) * 2;
#pragma unroll
    for (int mf = 0; mf < 4; ++mf) {
        const int hi = (wm + mf * 16) >> 4;          // h-row of this 16-row frag
        const int gh = h0 + hi;
        const size_t prow = (size_t)(n * IMG + gh * HW + w0);
        float* p0 = out + (prow + r0)     * COUT + nt * 128 + wn;
        float* p1 = out + (prow + r0 + 8) * COUT + nt * 128 + wn;
#pragma unroll
        for (int nb = 0; nb < 4; ++nb) {
            *(float2*)(p0 + nb * 8 + c0) = make_float2(acc[mf][nb][0], acc[mf][nb][1]);
            *(float2*)(p1 + nb * 8 + c0) = make_float2(acc[mf][nb][2], acc[mf][nb][3]);
        }
    }
}

// ---------------- launch ----------------
extern "C" void kernel_launch(void* const* d_in, const int* in_sizes, int n_in,
                              void* d_out, int out_size) {
    const float* x = (const float*)d_in[0];
    const float* w = (const float*)d_in[1];
    float* out = (float*)d_out;

    cudaFuncSetAttribute(conv_kernel,
                         cudaFuncAttributeMaxDynamicSharedMemorySize, DYN_SMEM);

    binarize_kernel<<<(COUT * KTOT + 255) / 256, 256>>>(w);
    quant_kernel<<<(NPOS * CIN / 4 + 255) / 256, 256>>>((const float4*)x);
    conv_kernel<<<NB * 14 * 7, 256, DYN_SMEM>>>(out, 0);   // 3136 CTAs
    conv_kernel<<<NB * 14 * 7, 256, DYN_SMEM>>>(out, 1);
}